// round 17
// baseline (speedup 1.0000x reference)
#include <cuda_runtime.h>

typedef unsigned long long u64;
typedef unsigned int u32;

#define MM    16
#define JJ    8
#define CINN  64
#define COUTN 64
#define HH    64
#define WW    64
#define TLW   16
#define TLH   16
#define XCOLS 24
#define XPIX  576
#define NCP   32
#define NTHREADS 512

/* smem layout (bytes): x tile then Tb */
#define TBP     52                 /* Tb row pitch in u32 words            */
#define TBLO    (16 * TBP)         /* u32 offset of lo plane               */
#define SM_TB   147456             /* x tile: 32cp*576*8B                  */
#define SMEM_BYTES (SM_TB + 2 * 16 * TBP * 4)   /* 154112 */

#define J4OFF   (4 * CINN * COUTN) /* w offset from j to j+4 (floats)      */

/* bf16x2 pack: low 16 = first arg, high 16 = second arg */
__device__ __forceinline__ u32 bf2(float lo, float hi) {
    u32 r; asm("cvt.rn.bf16x2.f32 %0, %1, %2;" : "=r"(r) : "f"(hi), "f"(lo)); return r;
}
__device__ __forceinline__ float bflo(u32 w) { return __uint_as_float(w << 16); }
__device__ __forceinline__ float bfhi(u32 w) { return __uint_as_float(w & 0xffff0000u); }

__device__ __forceinline__ void mma16816(float* d, const u32* a, const u32* b) {
    asm("mma.sync.aligned.m16n8k16.row.col.f32.bf16.bf16.f32 "
        "{%0,%1,%2,%3}, {%4,%5,%6,%7}, {%8,%9}, {%0,%1,%2,%3};"
        : "+f"(d[0]), "+f"(d[1]), "+f"(d[2]), "+f"(d[3])
        : "r"(a[0]), "r"(a[1]), "r"(a[2]), "r"(a[3]), "r"(b[0]), "r"(b[1]));
}

extern __shared__ char smem_raw[];

__global__ void __launch_bounds__(NTHREADS, 1)
bessel_conv_kernel(const float* __restrict__ x,
                   const float* __restrict__ T_real,
                   const float* __restrict__ T_imag,
                   const float* __restrict__ w_r,
                   const float* __restrict__ w_i,
                   const float* __restrict__ bias,
                   float* __restrict__ out)
{
    float2* xs2 = (float2*)smem_raw;                 /* [32 cp][576 px] */
    u32*    tb  = (u32*)(smem_raw + SM_TB);

    const int tid  = threadIdx.x;
    const int lane = tid & 31;
    const int wid  = tid >> 5;           /* 0..15: warp owns pixel row wid  */
    const int r4 = lane >> 2, t4 = lane & 3;
    const int tileX = blockIdx.x, tileY = blockIdx.y, b = blockIdx.z;

    /* ---- stage x tile (+4 halo, zero padded), cin-paired float2 ---- */
    {
        const int baseY = tileY * TLH - 4, baseX = tileX * TLW - 4;
        const float* xb = x + (size_t)b * CINN * HH * WW;
        for (int idx = tid; idx < NCP * XPIX; idx += NTHREADS) {
            int cp = idx / XPIX, rem = idx - cp * XPIX;
            int r = rem / XCOLS, c = rem - r * XCOLS;
            int iy = baseY + r, ix = baseX + c;
            float2 v = make_float2(0.f, 0.f);
            if (iy >= 0 && iy < HH && ix >= 0 && ix < WW) {
                const float* pb = xb + ((size_t)(2 * cp) * HH + iy) * WW + ix;
                v.x = pb[0]; v.y = pb[(size_t)HH * WW];
            }
            xs2[idx] = v;
        }
    }

    const int PA[6]  = {0, 1, 0, 2, 3, 2};
    const int PBR[6] = {0, 0, 1, 4, 4, 5};
    const int PBI[6] = {2, 2, 3, 0, 0, 1};

#pragma unroll 1
    for (int m = 0; m < MM; ++m) {
        __syncthreads();   /* all warps done reading prior Tb (and x staged at m=0) */

        /* ---- stage Tb (K=96 packing, verified round 16) ---- */
        {
            const float* Trm = T_real + m * 648;
            const float* Tim = T_imag + m * 648;
            for (int idx = tid; idx < 16 * 48; idx += NTHREADS) {
                int n = idx / 48, w = idx - n * 48;
                int a = w >> 3, tw = w & 7;
                int j = n >> 1;
                const float* src = (n & 1) ? Tim : Trm;
                int l0 = 2 * tw, l1 = l0 + 1;
                float v0, v1;
                if (a < 5) {
                    int k1a = 2 * a + (l0 >> 3), k2a = l0 & 7;
                    int k1b = 2 * a + (l1 >> 3), k2b = l1 & 7;
                    v0 = (k1a <= 8) ? src[(k1a * 9 + k2a) * 8 + j] : 0.f;
                    v1 = (k1b <= 8) ? src[(k1b * 9 + k2b) * 8 + j] : 0.f;
                } else {
                    v0 = (l0 <= 8) ? src[(l0 * 9 + 8) * 8 + j] : 0.f;
                    v1 = (l1 <= 8) ? src[(l1 * 9 + 8) * 8 + j] : 0.f;
                }
                u32 hi = bf2(v0, v1);
                u32 lo = bf2(v0 - bflo(hi), v1 - bfhi(hi));
                tb[n * TBP + w]        = hi;
                tb[TBLO + n * TBP + w] = lo;
            }
        }
        __syncthreads();   /* Tb visible; NO further syncs until next m */

        /* per-thread W gmem bases: j = t4 row, cout base r4 */
        const float* wrb = w_r + ((size_t)(m * JJ + t4) * CINN) * COUTN + r4;
        const float* wib = w_i + ((size_t)(m * JJ + t4) * CINN) * COUTN + r4;

        float Dk[8][2][4];               /* [ntile][re/im][frag] : 64 regs */
#pragma unroll
        for (int n = 0; n < 8; ++n)
#pragma unroll
            for (int e = 0; e < 2; ++e)
#pragma unroll
                for (int q = 0; q < 4; ++q) Dk[n][e][q] = 0.f;

#pragma unroll 1
        for (int cp = 0; cp < NCP; ++cp) {
            /* ---- Stage A: AD[cin][nt][4], K=96 in 6 chunks (round 16) ---- */
            float AD[2][2][4];
#pragma unroll
            for (int c = 0; c < 2; ++c)
#pragma unroll
                for (int n = 0; n < 2; ++n)
#pragma unroll
                    for (int q = 0; q < 4; ++q) AD[c][n][q] = 0.f;

            const float2* xt = xs2 + cp * XPIX;
            const int colA = r4 + 2 * t4;

#pragma unroll
            for (int a = 0; a < 5; ++a) {
                u32 bh[2][2], bl[2][2];
#pragma unroll
                for (int nt = 0; nt < 2; ++nt) {
                    int ni = (r4 + 8 * nt) * TBP + a * 8 + t4;
                    bh[nt][0] = tb[ni];        bh[nt][1] = tb[ni + 4];
                    bl[nt][0] = tb[TBLO + ni]; bl[nt][1] = tb[TBLO + ni + 4];
                }
                const float2* x0 = xt + (wid + 2 * a) * XCOLS + colA;
                u32 Ah[2][4], Al[2][4];
                {
                    float2 v0 = x0[0], v1 = x0[1], v2 = x0[8], v3 = x0[9];
#pragma unroll
                    for (int c = 0; c < 2; ++c) {
                        float e0 = c ? v0.y : v0.x, e1 = c ? v1.y : v1.x;
                        float e2 = c ? v2.y : v2.x, e3 = c ? v3.y : v3.x;
                        Ah[c][0] = bf2(e0, e1);
                        Al[c][0] = bf2(e0 - bflo(Ah[c][0]), e1 - bfhi(Ah[c][0]));
                        Ah[c][1] = bf2(e2, e3);
                        Al[c][1] = bf2(e2 - bflo(Ah[c][1]), e3 - bfhi(Ah[c][1]));
                    }
                }
                if (a < 4) {
                    const float2* x1 = x0 + XCOLS;
                    float2 v0 = x1[0], v1 = x1[1], v2 = x1[8], v3 = x1[9];
#pragma unroll
                    for (int c = 0; c < 2; ++c) {
                        float e0 = c ? v0.y : v0.x, e1 = c ? v1.y : v1.x;
                        float e2 = c ? v2.y : v2.x, e3 = c ? v3.y : v3.x;
                        Ah[c][2] = bf2(e0, e1);
                        Al[c][2] = bf2(e0 - bflo(Ah[c][2]), e1 - bfhi(Ah[c][2]));
                        Ah[c][3] = bf2(e2, e3);
                        Al[c][3] = bf2(e2 - bflo(Ah[c][3]), e3 - bfhi(Ah[c][3]));
                    }
                } else {
#pragma unroll
                    for (int c = 0; c < 2; ++c) {
                        Ah[c][2] = Ah[c][3] = 0u;
                        Al[c][2] = Al[c][3] = 0u;
                    }
                }
#pragma unroll
                for (int c = 0; c < 2; ++c)
#pragma unroll
                    for (int nt = 0; nt < 2; ++nt) {
                        mma16816(AD[c][nt], Ah[c], bh[nt]);
                        mma16816(AD[c][nt], Al[c], bh[nt]);
                        mma16816(AD[c][nt], Ah[c], bl[nt]);
                    }
            }
            /* ---- chunk 5: k2 == 8 column ---- */
            {
                u32 bh[2][2], bl[2][2];
#pragma unroll
                for (int nt = 0; nt < 2; ++nt) {
                    int ni = (r4 + 8 * nt) * TBP + 5 * 8 + t4;
                    bh[nt][0] = tb[ni];        bh[nt][1] = tb[ni + 4];
                    bl[nt][0] = tb[TBLO + ni]; bl[nt][1] = tb[TBLO + ni + 4];
                }
                float2 va = xt[(wid + 2 * t4) * XCOLS + r4 + 8];
                float2 vb = xt[(wid + 2 * t4 + 1) * XCOLS + r4 + 8];
                float2 vc = xt[(wid + 2 * t4) * XCOLS + r4 + 16];
                float2 vd = xt[(wid + 2 * t4 + 1) * XCOLS + r4 + 16];
                float2 ve = make_float2(0.f, 0.f), vf = make_float2(0.f, 0.f);
                if (t4 == 0) {
                    ve = xt[(wid + 8) * XCOLS + r4 + 8];
                    vf = xt[(wid + 8) * XCOLS + r4 + 16];
                }
                u32 Ah[2][4], Al[2][4];
#pragma unroll
                for (int c = 0; c < 2; ++c) {
                    float ea = c ? va.y : va.x, eb = c ? vb.y : vb.x;
                    float ec = c ? vc.y : vc.x, ed = c ? vd.y : vd.x;
                    float ee = c ? ve.y : ve.x, ef = c ? vf.y : vf.x;
                    Ah[c][0] = bf2(ea, eb);
                    Al[c][0] = bf2(ea - bflo(Ah[c][0]), eb - bfhi(Ah[c][0]));
                    Ah[c][1] = bf2(ec, ed);
                    Al[c][1] = bf2(ec - bflo(Ah[c][1]), ed - bfhi(Ah[c][1]));
                    Ah[c][2] = bf2(ee, 0.f);
                    Al[c][2] = bf2(ee - bflo(Ah[c][2]), 0.f);
                    Ah[c][3] = bf2(ef, 0.f);
                    Al[c][3] = bf2(ef - bflo(Ah[c][3]), 0.f);
                }
#pragma unroll
                for (int c = 0; c < 2; ++c)
#pragma unroll
                    for (int nt = 0; nt < 2; ++nt) {
                        mma16816(AD[c][nt], Ah[c], bh[nt]);
                        mma16816(AD[c][nt], Al[c], bh[nt]);
                        mma16816(AD[c][nt], Ah[c], bl[nt]);
                    }
            }

            /* ---- afr: Stage B A-fragments built LOCALLY from AD ----
               thread (r4,t4) owns U[px r4,r4+8][j=t4,t4+4][re,im] ==
               exactly its own m16n8k16 A fragment. No smem, no sync. */
            u32 afr[4][4];
#pragma unroll
            for (int c = 0; c < 2; ++c)
#pragma unroll
                for (int h = 0; h < 2; ++h) {
                    float e0 = AD[c][0][2 * h],     e1 = AD[c][1][2 * h];
                    u32 hr = bf2(e0, e1);
                    afr[0][2 * c + h] = hr;
                    afr[1][2 * c + h] = bf2(e0 - bflo(hr), e1 - bfhi(hr));
                    float f0 = AD[c][0][2 * h + 1], f1 = AD[c][1][2 * h + 1];
                    u32 hi2 = bf2(f0, f1);
                    afr[2][2 * c + h] = hi2;
                    afr[3][2 * c + h] = bf2(f0 - bflo(hi2), f1 - bfhi(hi2));
                }

            /* ---- Stage B: W straight from gmem into B-fragments ---- */
            const int cbase = cp * 2 * COUTN;
#pragma unroll
            for (int nt = 0; nt < 8; ++nt) {
                const int off0 = cbase + nt * 8;       /* cin 2cp   */
                const int off1 = off0 + COUTN;         /* cin 2cp+1 */
                float r00 = __ldg(wrb + off0), r04 = __ldg(wrb + J4OFF + off0);
                float r10 = __ldg(wrb + off1), r14 = __ldg(wrb + J4OFF + off1);
                float i00 = __ldg(wib + off0), i04 = __ldg(wib + J4OFF + off0);
                float i10 = __ldg(wib + off1), i14 = __ldg(wib + J4OFF + off1);
                u32 bfr[6][2];
                u32 h;
                h = bf2(r00, r04); bfr[0][0] = h;
                bfr[1][0] = bf2(r00 - bflo(h), r04 - bfhi(h));
                h = bf2(r10, r14); bfr[0][1] = h;
                bfr[1][1] = bf2(r10 - bflo(h), r14 - bfhi(h));
                h = bf2(i00, i04); bfr[2][0] = h;
                bfr[3][0] = bf2(i00 - bflo(h), i04 - bfhi(h));
                bfr[4][0] = h ^ 0x80008000u;
                bfr[5][0] = bfr[3][0] ^ 0x80008000u;
                h = bf2(i10, i14); bfr[2][1] = h;
                bfr[3][1] = bf2(i10 - bflo(h), i14 - bfhi(h));
                bfr[4][1] = h ^ 0x80008000u;
                bfr[5][1] = bfr[3][1] ^ 0x80008000u;
#pragma unroll
                for (int pi = 0; pi < 6; ++pi)
                    mma16816(Dk[nt][0], afr[PA[pi]], bfr[PBR[pi]]);
#pragma unroll
                for (int pi = 0; pi < 6; ++pi)
                    mma16816(Dk[nt][1], afr[PA[pi]], bfr[PBI[pi]]);
            }
        }

        /* ---- epilogue: |y|^2 RMW into out (m=0 initializes + bias) ---- */
#pragma unroll
        for (int nt = 0; nt < 8; ++nt) {
            const float* dR = Dk[nt][0];
            const float* dI = Dk[nt][1];
            const int c0 = nt * 8 + t4 * 2;
            float v00 = dR[0] * dR[0] + dI[0] * dI[0];
            float v01 = dR[1] * dR[1] + dI[1] * dI[1];
            float v10 = dR[2] * dR[2] + dI[2] * dI[2];
            float v11 = dR[3] * dR[3] + dI[3] * dI[3];
            float* ob = out + ((size_t)b * COUTN + c0) * (HH * WW)
                      + (tileY * TLH + wid) * WW + tileX * TLW;
            if (m == 0) {
                float b0 = __ldg(bias + c0), b1 = __ldg(bias + c0 + 1);
                ob[r4]                 = v00 + b0;
                ob[HH * WW + r4]       = v01 + b1;
                ob[r4 + 8]             = v10 + b0;
                ob[HH * WW + r4 + 8]   = v11 + b1;
            } else {
                ob[r4]               += v00;
                ob[HH * WW + r4]     += v01;
                ob[r4 + 8]           += v10;
                ob[HH * WW + r4 + 8] += v11;
            }
        }
    }
}

extern "C" void kernel_launch(void* const* d_in, const int* in_sizes, int n_in,
                              void* d_out, int out_size)
{
    (void)in_sizes; (void)n_in; (void)out_size;
    const float* x  = (const float*)d_in[0];
    const float* Tr = (const float*)d_in[1];
    const float* Ti = (const float*)d_in[2];
    const float* wr = (const float*)d_in[3];
    const float* wi = (const float*)d_in[4];
    const float* b  = (const float*)d_in[5];
    float* out = (float*)d_out;

    cudaFuncSetAttribute(bessel_conv_kernel,
                         cudaFuncAttributeMaxDynamicSharedMemorySize, SMEM_BYTES);

    dim3 grid(WW / TLW, HH / TLH, 32);   /* (4,4,32) = 512 CTAs */
    bessel_conv_kernel<<<grid, NTHREADS, SMEM_BYTES>>>(x, Tr, Ti, wr, wi, b, out);
}